// round 4
// baseline (speedup 1.0000x reference)
#include <cuda_runtime.h>
#include <cuda_bf16.h>

#define N_NODES 50000
#define NEDGE   800000
#define ETOT    850000
#define C       128
#define H       8
#define NEG_SLOPE 0.2f
#define GEMM_BLOCKS 1563     // ceil(50000/32)
#define HIST_BLOCKS 3321     // ceil(850000/256)

// ---------------- scratch ----------------
__device__ __align__(16) float g_h[N_NODES * C];
__device__ __align__(16) float g_acc[N_NODES * C];
__device__ float g_asrc[N_NODES * H];
__device__ float g_adst[N_NODES * H];
__device__ int   g_deg[N_NODES];
__device__ int   g_off[N_NODES];
__device__ int   g_cursor[N_NODES];
__device__ int   g_csrc[ETOT];
__device__ int   g_ecounter;
__device__ float g_colsum[C];
__device__ float g_colsq[C];
__device__ float g_scale[C];
__device__ float g_shift[C];

// ---------------- f32x2 helpers ----------------
__device__ __forceinline__ unsigned long long pack2(float lo, float hi) {
    unsigned long long r;
    asm("mov.b64 %0, {%1, %2};" : "=l"(r) : "f"(lo), "f"(hi));
    return r;
}
__device__ __forceinline__ void ffma2(unsigned long long& d,
                                      unsigned long long a, unsigned long long b) {
    asm("fma.rn.f32x2 %0, %1, %2, %0;" : "+l"(d) : "l"(a), "l"(b));
}
__device__ __forceinline__ float2 unpack2(unsigned long long v) {
    float2 f;
    asm("mov.b64 {%0, %1}, %2;" : "=f"(f.x), "=f"(f.y) : "l"(v));
    return f;
}

// ---------------- K0: zero counters ----------------
__global__ void k_zero() {
    int i = blockIdx.x * 256 + threadIdx.x;
    if (i < N_NODES) g_deg[i] = 0;
    if (i < C) { g_colsum[i] = 0.f; g_colsq[i] = 0.f; }
    if (i == 0) g_ecounter = 0;
}

// ---------------- K1: fused [GEMM + attention halves] | [degree histogram] ----------------
__global__ void k_gemm_hist(const float* __restrict__ x, const float* __restrict__ W,
                            const float* __restrict__ att_src, const float* __restrict__ att_dst,
                            const int* __restrict__ ei) {
    __shared__ unsigned long long xsd[32][C];   // x values duplicated as (v,v) pairs, 32KB
    int tid = threadIdx.x;

    if (blockIdx.x >= GEMM_BLOCKS) {
        // ---- histogram part ----
        int eid = (blockIdx.x - GEMM_BLOCKS) * 256 + tid;
        if (eid < ETOT) {
            int d = (eid < NEDGE) ? ei[NEDGE + eid] : (eid - NEDGE);
            atomicAdd(&g_deg[d], 1);
        }
        return;
    }

    // ---- GEMM part: 32 nodes per block ----
    int base = blockIdx.x * 32;
    for (int i = tid; i < 32 * 32; i += 256) {
        int node = i >> 5;
        int c4   = i & 31;
        int gn   = base + node;
        float4 v = (gn < N_NODES) ? ((const float4*)x)[gn * 32 + c4]
                                  : make_float4(0.f, 0.f, 0.f, 0.f);
        xsd[node][c4 * 4 + 0] = pack2(v.x, v.x);
        xsd[node][c4 * 4 + 1] = pack2(v.y, v.y);
        xsd[node][c4 * 4 + 2] = pack2(v.z, v.z);
        xsd[node][c4 * 4 + 3] = pack2(v.w, v.w);
    }
    __syncthreads();

    int cg = tid & 31;   // column group: cols [4cg, 4cg+3]
    int ng = tid >> 5;   // node group:   nodes ng*4 .. ng*4+3

    unsigned long long acc[4][2];
    #pragma unroll
    for (int j = 0; j < 4; j++) { acc[j][0] = 0ull; acc[j][1] = 0ull; }

    const ulonglong2* W2 = (const ulonglong2*)W;   // row k: 32 ulonglong2 of 16B
    const unsigned long long* xr0 = xsd[ng * 4 + 0];
    const unsigned long long* xr1 = xsd[ng * 4 + 1];
    const unsigned long long* xr2 = xsd[ng * 4 + 2];
    const unsigned long long* xr3 = xsd[ng * 4 + 3];

    #pragma unroll 4
    for (int k = 0; k < C; k++) {
        ulonglong2 w = W2[k * 32 + cg];
        unsigned long long x0 = xr0[k], x1 = xr1[k], x2 = xr2[k], x3 = xr3[k];
        ffma2(acc[0][0], w.x, x0); ffma2(acc[0][1], w.y, x0);
        ffma2(acc[1][0], w.x, x1); ffma2(acc[1][1], w.y, x1);
        ffma2(acc[2][0], w.x, x2); ffma2(acc[2][1], w.y, x2);
        ffma2(acc[3][0], w.x, x3); ffma2(acc[3][1], w.y, x3);
    }

    float4 as = ((const float4*)att_src)[cg];
    float4 ad = ((const float4*)att_dst)[cg];

    #pragma unroll
    for (int j = 0; j < 4; j++) {
        float2 lo = unpack2(acc[j][0]);
        float2 hi = unpack2(acc[j][1]);
        float4 a = make_float4(lo.x, lo.y, hi.x, hi.y);
        float ps = a.x*as.x + a.y*as.y + a.z*as.z + a.w*as.w;
        float pd = a.x*ad.x + a.y*ad.y + a.z*ad.z + a.w*ad.w;
        ps += __shfl_xor_sync(0xffffffffu, ps, 1);
        ps += __shfl_xor_sync(0xffffffffu, ps, 2);
        pd += __shfl_xor_sync(0xffffffffu, pd, 1);
        pd += __shfl_xor_sync(0xffffffffu, pd, 2);
        int n = base + ng * 4 + j;
        if (n < N_NODES) {
            ((float4*)g_h)[n * 32 + cg] = a;
            if ((cg & 3) == 0) {
                int hd = cg >> 2;
                g_asrc[n * H + hd] = ps;
                g_adst[n * H + hd] = pd;
            }
        }
    }
}

// ---------------- K2: offsets via warp-scan + one atomic per warp ----------------
__global__ void k_offsets() {
    int i    = blockIdx.x * 256 + threadIdx.x;
    int lane = threadIdx.x & 31;
    int v = (i < N_NODES) ? g_deg[i] : 0;
    int incl = v;
    #pragma unroll
    for (int o = 1; o < 32; o <<= 1) {
        int t = __shfl_up_sync(0xffffffffu, incl, o);
        if (lane >= o) incl += t;
    }
    int total = __shfl_sync(0xffffffffu, incl, 31);
    int wbase = 0;
    if (lane == 0) wbase = atomicAdd(&g_ecounter, total);
    wbase = __shfl_sync(0xffffffffu, wbase, 0);
    if (i < N_NODES) {
        int o = wbase + incl - v;
        g_off[i]    = o;
        g_cursor[i] = o;
    }
}

// ---------------- K3: fill CSR ----------------
__global__ void k_fill(const int* __restrict__ ei) {
    int eid = blockIdx.x * 256 + threadIdx.x;
    if (eid >= ETOT) return;
    int s, d;
    if (eid < NEDGE) { s = ei[eid]; d = ei[NEDGE + eid]; }
    else             { s = d = eid - NEDGE; }
    int pos = atomicAdd(&g_cursor[d], 1);
    g_csrc[pos] = s;
}

// ---------------- K4: warp-per-dst single-pass softmax-aggregate + fused BN stats ----------------
__global__ void k_aggregate() {
    __shared__ float ssum[C];
    __shared__ float ssq[C];
    int t = threadIdx.x;
    if (t < C) ssum[t] = 0.f; else ssq[t - C] = 0.f;
    __syncthreads();

    int warp = blockIdx.x * 8 + (t >> 5);
    int lane = t & 31;
    int hd   = lane >> 2;

    if (warp < N_NODES) {
        int beg = g_off[warp];
        int end = beg + g_deg[warp];
        float adst = g_adst[warp * H + hd];

        float den = 0.f;
        float4 acc = make_float4(0.f, 0.f, 0.f, 0.f);
        for (int p = beg; p < end; p++) {
            int s = g_csrc[p];
            float e = g_asrc[s * H + hd] + adst;
            e = (e > 0.f) ? e : NEG_SLOPE * e;
            float ex = __expf(e);
            den += ex;
            float4 v = ((const float4*)g_h)[s * 32 + lane];
            acc.x += ex * v.x; acc.y += ex * v.y;
            acc.z += ex * v.z; acc.w += ex * v.w;
        }
        float inv = 1.f / (den + 1e-16f);
        acc.x *= inv; acc.y *= inv; acc.z *= inv; acc.w *= inv;
        ((float4*)g_acc)[warp * 32 + lane] = acc;

        int c = lane * 4;
        atomicAdd(&ssum[c + 0], acc.x); atomicAdd(&ssq[c + 0], acc.x * acc.x);
        atomicAdd(&ssum[c + 1], acc.y); atomicAdd(&ssq[c + 1], acc.y * acc.y);
        atomicAdd(&ssum[c + 2], acc.z); atomicAdd(&ssq[c + 2], acc.z * acc.z);
        atomicAdd(&ssum[c + 3], acc.w); atomicAdd(&ssq[c + 3], acc.w * acc.w);
    }
    __syncthreads();
    if (t < C) {
        atomicAdd(&g_colsum[t], ssum[t]);
        atomicAdd(&g_colsq[t], ssq[t]);
    }
}

// ---------------- K5: fold stats (bias cancels in training-mode BN) ----------------
__global__ void k_scale(const float* __restrict__ gamma, const float* __restrict__ beta) {
    int c = threadIdx.x;
    float inv_n = 1.f / (float)N_NODES;
    float mean = g_colsum[c] * inv_n;
    float var  = g_colsq[c] * inv_n - mean * mean;
    float sc   = gamma[c] * rsqrtf(var + 1e-5f);
    g_scale[c] = sc;
    g_shift[c] = beta[c] - mean * sc;
}

// ---------------- K6: normalize + ReLU ----------------
__global__ void k_final(float* __restrict__ out) {
    int idx = blockIdx.x * 256 + threadIdx.x;
    if (idx >= N_NODES * C) return;
    int c = idx & (C - 1);
    float y = g_acc[idx] * g_scale[c] + g_shift[c];
    out[idx] = fmaxf(y, 0.f);
}

// ---------------- launch ----------------
extern "C" void kernel_launch(void* const* d_in, const int* in_sizes, int n_in,
                              void* d_out, int out_size) {
    const float* x       = (const float*)d_in[0];
    const int*   ei      = (const int*)d_in[1];
    const float* W       = (const float*)d_in[2];
    const float* att_src = (const float*)d_in[3];
    const float* att_dst = (const float*)d_in[4];
    const float* gamma   = (const float*)d_in[6];
    const float* beta    = (const float*)d_in[7];
    float*       out     = (float*)d_out;

    k_zero<<<(N_NODES + 255) / 256, 256>>>();
    k_gemm_hist<<<GEMM_BLOCKS + HIST_BLOCKS, 256>>>(x, W, att_src, att_dst, ei);
    k_offsets<<<(N_NODES + 255) / 256, 256>>>();
    k_fill<<<(ETOT + 255) / 256, 256>>>(ei);
    k_aggregate<<<(N_NODES + 7) / 8, 256>>>();
    k_scale<<<1, C>>>(gamma, beta);
    k_final<<<(N_NODES * C + 255) / 256, 256>>>(out);
}

// round 5
// speedup vs baseline: 1.0456x; 1.0456x over previous
#include <cuda_runtime.h>
#include <cuda_bf16.h>

#define N_NODES 50000
#define NEDGE   800000
#define ETOT    850000
#define C       128
#define H       8
#define NEG_SLOPE 0.2f
#define GEMM_BLOCKS 1563     // ceil(50000/32)
#define HIST_BLOCKS 3125     // ceil(800000/256)

// ---------------- scratch (zero-initialized at module load) ----------------
__device__ __align__(16) float g_h[N_NODES * C];
__device__ __align__(16) float g_acc[N_NODES * C];
__device__ float g_asrc[N_NODES * H];
__device__ float g_adst[N_NODES * H];
__device__ int   g_deg[N_NODES];     // real-edge in-degree (self loop added analytically)
__device__ int   g_off[N_NODES];
__device__ int   g_cursor[N_NODES];
__device__ int   g_csrc[ETOT];
__device__ int   g_ecounter;
__device__ float g_colsum[C];
__device__ float g_colsq[C];

// ---------------- f32x2 helpers ----------------
__device__ __forceinline__ unsigned long long pack2(float lo, float hi) {
    unsigned long long r;
    asm("mov.b64 %0, {%1, %2};" : "=l"(r) : "f"(lo), "f"(hi));
    return r;
}
__device__ __forceinline__ void ffma2(unsigned long long& d,
                                      unsigned long long a, unsigned long long b) {
    asm("fma.rn.f32x2 %0, %1, %2, %0;" : "+l"(d) : "l"(a), "l"(b));
}
__device__ __forceinline__ float2 unpack2(unsigned long long v) {
    float2 f;
    asm("mov.b64 {%0, %1}, %2;" : "=f"(f.x), "=f"(f.y) : "l"(v));
    return f;
}

// ---------------- K1: fused [GEMM + attention halves] | [degree histogram] ----------------
__global__ void k_gemm_hist(const float* __restrict__ x, const float* __restrict__ W,
                            const float* __restrict__ att_src, const float* __restrict__ att_dst,
                            const int* __restrict__ ei) {
    __shared__ unsigned long long xsd[32][C];
    int tid = threadIdx.x;

    if (blockIdx.x >= GEMM_BLOCKS) {
        int eid = (blockIdx.x - GEMM_BLOCKS) * 256 + tid;
        if (eid < NEDGE) atomicAdd(&g_deg[ei[NEDGE + eid]], 1);
        return;
    }

    int base = blockIdx.x * 32;
    for (int i = tid; i < 32 * 32; i += 256) {
        int node = i >> 5;
        int c4   = i & 31;
        int gn   = base + node;
        float4 v = (gn < N_NODES) ? ((const float4*)x)[gn * 32 + c4]
                                  : make_float4(0.f, 0.f, 0.f, 0.f);
        xsd[node][c4 * 4 + 0] = pack2(v.x, v.x);
        xsd[node][c4 * 4 + 1] = pack2(v.y, v.y);
        xsd[node][c4 * 4 + 2] = pack2(v.z, v.z);
        xsd[node][c4 * 4 + 3] = pack2(v.w, v.w);
    }
    __syncthreads();

    int cg = tid & 31;
    int ng = tid >> 5;

    unsigned long long acc[4][2];
    #pragma unroll
    for (int j = 0; j < 4; j++) { acc[j][0] = 0ull; acc[j][1] = 0ull; }

    const ulonglong2* W2 = (const ulonglong2*)W;
    const unsigned long long* xr0 = xsd[ng * 4 + 0];
    const unsigned long long* xr1 = xsd[ng * 4 + 1];
    const unsigned long long* xr2 = xsd[ng * 4 + 2];
    const unsigned long long* xr3 = xsd[ng * 4 + 3];

    #pragma unroll 4
    for (int k = 0; k < C; k++) {
        ulonglong2 w = W2[k * 32 + cg];
        unsigned long long x0 = xr0[k], x1 = xr1[k], x2 = xr2[k], x3 = xr3[k];
        ffma2(acc[0][0], w.x, x0); ffma2(acc[0][1], w.y, x0);
        ffma2(acc[1][0], w.x, x1); ffma2(acc[1][1], w.y, x1);
        ffma2(acc[2][0], w.x, x2); ffma2(acc[2][1], w.y, x2);
        ffma2(acc[3][0], w.x, x3); ffma2(acc[3][1], w.y, x3);
    }

    float4 as = ((const float4*)att_src)[cg];
    float4 ad = ((const float4*)att_dst)[cg];

    #pragma unroll
    for (int j = 0; j < 4; j++) {
        float2 lo = unpack2(acc[j][0]);
        float2 hi = unpack2(acc[j][1]);
        float4 a = make_float4(lo.x, lo.y, hi.x, hi.y);
        float ps = a.x*as.x + a.y*as.y + a.z*as.z + a.w*as.w;
        float pd = a.x*ad.x + a.y*ad.y + a.z*ad.z + a.w*ad.w;
        ps += __shfl_xor_sync(0xffffffffu, ps, 1);
        ps += __shfl_xor_sync(0xffffffffu, ps, 2);
        pd += __shfl_xor_sync(0xffffffffu, pd, 1);
        pd += __shfl_xor_sync(0xffffffffu, pd, 2);
        int n = base + ng * 4 + j;
        if (n < N_NODES) {
            ((float4*)g_h)[n * 32 + cg] = a;
            if ((cg & 3) == 0) {
                int hd = cg >> 2;
                g_asrc[n * H + hd] = ps;
                g_adst[n * H + hd] = pd;
            }
        }
    }
}

// ---------------- K2: offsets (warp scan + 1 atomic/warp) + self-loop placement ----------------
__global__ void k_offsets() {
    int i    = blockIdx.x * 256 + threadIdx.x;
    int lane = threadIdx.x & 31;
    int v = (i < N_NODES) ? (g_deg[i] + 1) : 0;   // +1 = self loop
    int incl = v;
    #pragma unroll
    for (int o = 1; o < 32; o <<= 1) {
        int t = __shfl_up_sync(0xffffffffu, incl, o);
        if (lane >= o) incl += t;
    }
    int total = __shfl_sync(0xffffffffu, incl, 31);
    int wbase = 0;
    if (lane == 0) wbase = atomicAdd(&g_ecounter, total);
    wbase = __shfl_sync(0xffffffffu, wbase, 0);
    if (i < N_NODES) {
        int o = wbase + incl - v;
        g_off[i]    = o;
        g_csrc[o]   = i;       // self loop goes in slot 0 of the segment
        g_cursor[i] = o + 1;
    }
}

// ---------------- K3: fill CSR with real edges ----------------
__global__ void k_fill(const int* __restrict__ ei) {
    int eid = blockIdx.x * 256 + threadIdx.x;
    if (eid >= NEDGE) return;
    int s = ei[eid];
    int d = ei[NEDGE + eid];
    int pos = atomicAdd(&g_cursor[d], 1);
    g_csrc[pos] = s;
}

// ---------------- K4: warp-per-dst single-pass softmax-aggregate + fused BN stats ----------------
__global__ void k_aggregate() {
    __shared__ float ssum[C];
    __shared__ float ssq[C];
    int t = threadIdx.x;
    if (t < C) ssum[t] = 0.f; else ssq[t - C] = 0.f;
    __syncthreads();

    int warp = blockIdx.x * 8 + (t >> 5);
    int lane = t & 31;
    int hd   = lane >> 2;

    if (warp < N_NODES) {
        int beg = g_off[warp];
        int end = beg + g_deg[warp] + 1;
        float adst = g_adst[warp * H + hd];

        float den = 0.f;
        float4 acc = make_float4(0.f, 0.f, 0.f, 0.f);

        for (int bp = beg; bp < end; bp += 32) {
            int myp = bp + lane;
            int sv = (myp < end) ? g_csrc[myp] : 0;   // coalesced segment load
            int cnt = min(32, end - bp);
            int j = 0;
            for (; j + 2 <= cnt; j += 2) {
                int sA = __shfl_sync(0xffffffffu, sv, j);
                int sB = __shfl_sync(0xffffffffu, sv, j + 1);
                float eA = g_asrc[sA * H + hd] + adst;
                float eB = g_asrc[sB * H + hd] + adst;
                float4 vA = ((const float4*)g_h)[sA * 32 + lane];
                float4 vB = ((const float4*)g_h)[sB * 32 + lane];
                eA = (eA > 0.f) ? eA : NEG_SLOPE * eA;
                eB = (eB > 0.f) ? eB : NEG_SLOPE * eB;
                float exA = __expf(eA);
                float exB = __expf(eB);
                den += exA + exB;
                acc.x += exA * vA.x; acc.y += exA * vA.y;
                acc.z += exA * vA.z; acc.w += exA * vA.w;
                acc.x += exB * vB.x; acc.y += exB * vB.y;
                acc.z += exB * vB.z; acc.w += exB * vB.w;
            }
            if (j < cnt) {
                int s = __shfl_sync(0xffffffffu, sv, j);
                float e = g_asrc[s * H + hd] + adst;
                e = (e > 0.f) ? e : NEG_SLOPE * e;
                float ex = __expf(e);
                den += ex;
                float4 v = ((const float4*)g_h)[s * 32 + lane];
                acc.x += ex * v.x; acc.y += ex * v.y;
                acc.z += ex * v.z; acc.w += ex * v.w;
            }
        }

        float inv = 1.f / (den + 1e-16f);
        acc.x *= inv; acc.y *= inv; acc.z *= inv; acc.w *= inv;
        ((float4*)g_acc)[warp * 32 + lane] = acc;

        int c = lane * 4;
        atomicAdd(&ssum[c + 0], acc.x); atomicAdd(&ssq[c + 0], acc.x * acc.x);
        atomicAdd(&ssum[c + 1], acc.y); atomicAdd(&ssq[c + 1], acc.y * acc.y);
        atomicAdd(&ssum[c + 2], acc.z); atomicAdd(&ssq[c + 2], acc.z * acc.z);
        atomicAdd(&ssum[c + 3], acc.w); atomicAdd(&ssq[c + 3], acc.w * acc.w);
    }
    __syncthreads();
    if (t < C) {
        atomicAdd(&g_colsum[t], ssum[t]);
        atomicAdd(&g_colsq[t], ssq[t]);
    }
}

// ---------------- K5: normalize + ReLU (scale/shift computed in-block) ----------------
__global__ void k_final(const float* __restrict__ gamma, const float* __restrict__ beta,
                        float* __restrict__ out) {
    __shared__ float sscale[C];
    __shared__ float sshift[C];
    int t = threadIdx.x;
    if (t < C) {
        float inv_n = 1.f / (float)N_NODES;
        float mean = g_colsum[t] * inv_n;
        float var  = g_colsq[t] * inv_n - mean * mean;
        float sc   = gamma[t] * rsqrtf(var + 1e-5f);
        sscale[t] = sc;
        sshift[t] = beta[t] - mean * sc;
    }
    __syncthreads();
    int v4 = blockIdx.x * 256 + t;                 // float4 index
    if (v4 < N_NODES * 32) {
        int cb = (v4 & 31) * 4;                    // column base
        float4 a = ((const float4*)g_acc)[v4];
        float4 r;
        r.x = fmaxf(a.x * sscale[cb + 0] + sshift[cb + 0], 0.f);
        r.y = fmaxf(a.y * sscale[cb + 1] + sshift[cb + 1], 0.f);
        r.z = fmaxf(a.z * sscale[cb + 2] + sshift[cb + 2], 0.f);
        r.w = fmaxf(a.w * sscale[cb + 3] + sshift[cb + 3], 0.f);
        ((float4*)out)[v4] = r;
    }
}

// ---------------- K6: cleanup — restore zeroed counters for the next invocation ----------------
__global__ void k_cleanup() {
    int i = blockIdx.x * 256 + threadIdx.x;
    if (i < N_NODES) g_deg[i] = 0;
    if (i < C) { g_colsum[i] = 0.f; g_colsq[i] = 0.f; }
    if (i == 0) g_ecounter = 0;
}

// ---------------- launch ----------------
extern "C" void kernel_launch(void* const* d_in, const int* in_sizes, int n_in,
                              void* d_out, int out_size) {
    const float* x       = (const float*)d_in[0];
    const int*   ei      = (const int*)d_in[1];
    const float* W       = (const float*)d_in[2];
    const float* att_src = (const float*)d_in[3];
    const float* att_dst = (const float*)d_in[4];
    const float* gamma   = (const float*)d_in[6];
    const float* beta    = (const float*)d_in[7];
    float*       out     = (float*)d_out;

    k_gemm_hist<<<GEMM_BLOCKS + HIST_BLOCKS, 256>>>(x, W, att_src, att_dst, ei);
    k_offsets<<<(N_NODES + 255) / 256, 256>>>();
    k_fill<<<(NEDGE + 255) / 256, 256>>>(ei);
    k_aggregate<<<(N_NODES + 7) / 8, 256>>>();            // <- profiled launch (index 3)
    k_final<<<(N_NODES * 32 + 255) / 256, 256>>>(gamma, beta, out);
    k_cleanup<<<(N_NODES + 255) / 256, 256>>>();
}

// round 6
// speedup vs baseline: 1.0696x; 1.0229x over previous
#include <cuda_runtime.h>
#include <cuda_bf16.h>

#define N_NODES 50000
#define NEDGE   800000
#define ETOT    850000
#define C       128
#define H       8
#define NEG_SLOPE 0.2f
#define GEMM_BLOCKS 1563     // ceil(50000/32)
#define HIST_BLOCKS 1563     // ceil(800000/512), 4 edges/thread @128 threads

// ---------------- scratch (zero-initialized at module load) ----------------
__device__ __align__(16) float g_h[N_NODES * C];
__device__ __align__(16) float g_acc[N_NODES * C];
__device__ float g_asrc[N_NODES * H];
__device__ float g_adst[N_NODES * H];
__device__ int   g_deg[N_NODES];
__device__ int   g_off[N_NODES];
__device__ int   g_cursor[N_NODES];
__device__ int   g_csrc[ETOT];
__device__ int   g_ecounter;
__device__ float g_colsum[C];
__device__ float g_colsq[C];

// ---------------- f32x2 helpers ----------------
__device__ __forceinline__ unsigned long long pack2(float lo, float hi) {
    unsigned long long r;
    asm("mov.b64 %0, {%1, %2};" : "=l"(r) : "f"(lo), "f"(hi));
    return r;
}
__device__ __forceinline__ void ffma2(unsigned long long& d,
                                      unsigned long long a, unsigned long long b) {
    asm("fma.rn.f32x2 %0, %1, %2, %0;" : "+l"(d) : "l"(a), "l"(b));
}
__device__ __forceinline__ float2 unpack2(unsigned long long v) {
    float2 f;
    asm("mov.b64 {%0, %1}, %2;" : "=f"(f.x), "=f"(f.y) : "l"(v));
    return f;
}

// ---------------- K1: fused [GEMM 8n x 4c register-blocked] | [degree histogram] ----------------
// 128 threads/block. GEMM: 32 nodes/block; warp w handles nodes w*8..w*8+7; lane=cg cols 4cg..4cg+3.
__global__ void k_gemm_hist(const float* __restrict__ x, const float* __restrict__ W,
                            const float* __restrict__ att_src, const float* __restrict__ att_dst,
                            const int* __restrict__ ei) {
    __shared__ unsigned long long xsd[32][C];   // 32KB: x dup'd as (v,v)
    int tid = threadIdx.x;

    if (blockIdx.x >= GEMM_BLOCKS) {
        int base = (blockIdx.x - GEMM_BLOCKS) * 512 + tid;
        #pragma unroll
        for (int r = 0; r < 4; r++) {
            int eid = base + r * 128;
            if (eid < NEDGE) atomicAdd(&g_deg[ei[NEDGE + eid]], 1);
        }
        return;
    }

    int nbase = blockIdx.x * 32;
    for (int i = tid; i < 32 * 32; i += 128) {
        int node = i >> 5;
        int c4   = i & 31;
        int gn   = nbase + node;
        float4 v = (gn < N_NODES) ? ((const float4*)x)[gn * 32 + c4]
                                  : make_float4(0.f, 0.f, 0.f, 0.f);
        xsd[node][c4 * 4 + 0] = pack2(v.x, v.x);
        xsd[node][c4 * 4 + 1] = pack2(v.y, v.y);
        xsd[node][c4 * 4 + 2] = pack2(v.z, v.z);
        xsd[node][c4 * 4 + 3] = pack2(v.w, v.w);
    }
    __syncthreads();

    int cg = tid & 31;
    int wp = tid >> 5;                  // 0..3, nodes wp*8..wp*8+7
    const unsigned long long* xr = xsd[wp * 8];   // rows are contiguous: xr[j*C + k]

    unsigned long long acc[8][2];
    #pragma unroll
    for (int j = 0; j < 8; j++) { acc[j][0] = 0ull; acc[j][1] = 0ull; }

    const ulonglong2* W2 = (const ulonglong2*)W;

    #pragma unroll 2
    for (int k = 0; k < C; k++) {
        ulonglong2 w = W2[k * 32 + cg];
        #pragma unroll
        for (int j = 0; j < 8; j++) {
            unsigned long long xv = xr[j * C + k];
            ffma2(acc[j][0], w.x, xv);
            ffma2(acc[j][1], w.y, xv);
        }
    }

    float4 as = ((const float4*)att_src)[cg];
    float4 ad = ((const float4*)att_dst)[cg];

    #pragma unroll
    for (int j = 0; j < 8; j++) {
        float2 lo = unpack2(acc[j][0]);
        float2 hi = unpack2(acc[j][1]);
        float4 a = make_float4(lo.x, lo.y, hi.x, hi.y);
        float ps = a.x*as.x + a.y*as.y + a.z*as.z + a.w*as.w;
        float pd = a.x*ad.x + a.y*ad.y + a.z*ad.z + a.w*ad.w;
        ps += __shfl_xor_sync(0xffffffffu, ps, 1);
        ps += __shfl_xor_sync(0xffffffffu, ps, 2);
        pd += __shfl_xor_sync(0xffffffffu, pd, 1);
        pd += __shfl_xor_sync(0xffffffffu, pd, 2);
        int n = nbase + wp * 8 + j;
        if (n < N_NODES) {
            ((float4*)g_h)[n * 32 + cg] = a;
            if ((cg & 3) == 0) {
                int hd = cg >> 2;
                g_asrc[n * H + hd] = ps;
                g_adst[n * H + hd] = pd;
            }
        }
    }
}

// ---------------- K2: offsets (warp scan + 1 atomic/warp) + self-loop placement ----------------
__global__ void k_offsets() {
    int i    = blockIdx.x * 256 + threadIdx.x;
    int lane = threadIdx.x & 31;
    int v = (i < N_NODES) ? (g_deg[i] + 1) : 0;
    int incl = v;
    #pragma unroll
    for (int o = 1; o < 32; o <<= 1) {
        int t = __shfl_up_sync(0xffffffffu, incl, o);
        if (lane >= o) incl += t;
    }
    int total = __shfl_sync(0xffffffffu, incl, 31);
    int wbase = 0;
    if (lane == 0) wbase = atomicAdd(&g_ecounter, total);
    wbase = __shfl_sync(0xffffffffu, wbase, 0);
    if (i < N_NODES) {
        int o = wbase + incl - v;
        g_off[i]    = o;
        g_csrc[o]   = i;
        g_cursor[i] = o + 1;
    }
}

// ---------------- K3: fill CSR with real edges ----------------
__global__ void k_fill(const int* __restrict__ ei) {
    int eid = blockIdx.x * 256 + threadIdx.x;
    if (eid >= NEDGE) return;
    int s = ei[eid];
    int d = ei[NEDGE + eid];
    int pos = atomicAdd(&g_cursor[d], 1);
    g_csrc[pos] = s;
}

// ---------------- K4: warp-per-dst single-pass softmax-aggregate + fused BN stats ----------------
__global__ void k_aggregate() {
    __shared__ float ssum[C];
    __shared__ float ssq[C];
    int t = threadIdx.x;
    if (t < C) ssum[t] = 0.f; else ssq[t - C] = 0.f;
    __syncthreads();

    int warp = blockIdx.x * 8 + (t >> 5);
    int lane = t & 31;
    int hd   = lane >> 2;

    if (warp < N_NODES) {
        int beg = g_off[warp];
        int end = beg + g_deg[warp] + 1;
        float adst = g_adst[warp * H + hd];

        float den = 0.f;
        float4 acc = make_float4(0.f, 0.f, 0.f, 0.f);

        for (int bp = beg; bp < end; bp += 32) {
            int myp = bp + lane;
            int sv = (myp < end) ? g_csrc[myp] : 0;
            int cnt = min(32, end - bp);
            int j = 0;
            for (; j + 4 <= cnt; j += 4) {
                int s0 = __shfl_sync(0xffffffffu, sv, j);
                int s1 = __shfl_sync(0xffffffffu, sv, j + 1);
                int s2 = __shfl_sync(0xffffffffu, sv, j + 2);
                int s3 = __shfl_sync(0xffffffffu, sv, j + 3);
                // issue all 8 loads before any use
                float e0 = g_asrc[s0 * H + hd];
                float e1 = g_asrc[s1 * H + hd];
                float e2 = g_asrc[s2 * H + hd];
                float e3 = g_asrc[s3 * H + hd];
                float4 v0 = ((const float4*)g_h)[s0 * 32 + lane];
                float4 v1 = ((const float4*)g_h)[s1 * 32 + lane];
                float4 v2 = ((const float4*)g_h)[s2 * 32 + lane];
                float4 v3 = ((const float4*)g_h)[s3 * 32 + lane];
                e0 += adst; e1 += adst; e2 += adst; e3 += adst;
                e0 = (e0 > 0.f) ? e0 : NEG_SLOPE * e0;
                e1 = (e1 > 0.f) ? e1 : NEG_SLOPE * e1;
                e2 = (e2 > 0.f) ? e2 : NEG_SLOPE * e2;
                e3 = (e3 > 0.f) ? e3 : NEG_SLOPE * e3;
                float x0 = __expf(e0), x1 = __expf(e1);
                float x2 = __expf(e2), x3 = __expf(e3);
                den += (x0 + x1) + (x2 + x3);
                acc.x += x0 * v0.x; acc.y += x0 * v0.y; acc.z += x0 * v0.z; acc.w += x0 * v0.w;
                acc.x += x1 * v1.x; acc.y += x1 * v1.y; acc.z += x1 * v1.z; acc.w += x1 * v1.w;
                acc.x += x2 * v2.x; acc.y += x2 * v2.y; acc.z += x2 * v2.z; acc.w += x2 * v2.w;
                acc.x += x3 * v3.x; acc.y += x3 * v3.y; acc.z += x3 * v3.z; acc.w += x3 * v3.w;
            }
            for (; j < cnt; j++) {
                int s = __shfl_sync(0xffffffffu, sv, j);
                float e = g_asrc[s * H + hd] + adst;
                e = (e > 0.f) ? e : NEG_SLOPE * e;
                float ex = __expf(e);
                den += ex;
                float4 v = ((const float4*)g_h)[s * 32 + lane];
                acc.x += ex * v.x; acc.y += ex * v.y;
                acc.z += ex * v.z; acc.w += ex * v.w;
            }
        }

        float inv = 1.f / (den + 1e-16f);
        acc.x *= inv; acc.y *= inv; acc.z *= inv; acc.w *= inv;
        ((float4*)g_acc)[warp * 32 + lane] = acc;

        int c = lane * 4;
        atomicAdd(&ssum[c + 0], acc.x); atomicAdd(&ssq[c + 0], acc.x * acc.x);
        atomicAdd(&ssum[c + 1], acc.y); atomicAdd(&ssq[c + 1], acc.y * acc.y);
        atomicAdd(&ssum[c + 2], acc.z); atomicAdd(&ssq[c + 2], acc.z * acc.z);
        atomicAdd(&ssum[c + 3], acc.w); atomicAdd(&ssq[c + 3], acc.w * acc.w);
    }
    __syncthreads();
    if (t < C) {
        atomicAdd(&g_colsum[t], ssum[t]);
        atomicAdd(&g_colsq[t], ssq[t]);
    }
}

// ---------------- K5: normalize + ReLU ----------------
__global__ void k_final(const float* __restrict__ gamma, const float* __restrict__ beta,
                        float* __restrict__ out) {
    __shared__ float sscale[C];
    __shared__ float sshift[C];
    int t = threadIdx.x;
    if (t < C) {
        float inv_n = 1.f / (float)N_NODES;
        float mean = g_colsum[t] * inv_n;
        float var  = g_colsq[t] * inv_n - mean * mean;
        float sc   = gamma[t] * rsqrtf(var + 1e-5f);
        sscale[t] = sc;
        sshift[t] = beta[t] - mean * sc;
    }
    __syncthreads();
    int v4 = blockIdx.x * 256 + t;
    if (v4 < N_NODES * 32) {
        int cb = (v4 & 31) * 4;
        float4 a = ((const float4*)g_acc)[v4];
        float4 r;
        r.x = fmaxf(a.x * sscale[cb + 0] + sshift[cb + 0], 0.f);
        r.y = fmaxf(a.y * sscale[cb + 1] + sshift[cb + 1], 0.f);
        r.z = fmaxf(a.z * sscale[cb + 2] + sshift[cb + 2], 0.f);
        r.w = fmaxf(a.w * sscale[cb + 3] + sshift[cb + 3], 0.f);
        ((float4*)out)[v4] = r;
    }
}

// ---------------- K6: cleanup for next invocation ----------------
__global__ void k_cleanup() {
    int i = blockIdx.x * 256 + threadIdx.x;
    if (i < N_NODES) g_deg[i] = 0;
    if (i < C) { g_colsum[i] = 0.f; g_colsq[i] = 0.f; }
    if (i == 0) g_ecounter = 0;
}

// ---------------- launch ----------------
extern "C" void kernel_launch(void* const* d_in, const int* in_sizes, int n_in,
                              void* d_out, int out_size) {
    const float* x       = (const float*)d_in[0];
    const int*   ei      = (const int*)d_in[1];
    const float* W       = (const float*)d_in[2];
    const float* att_src = (const float*)d_in[3];
    const float* att_dst = (const float*)d_in[4];
    const float* gamma   = (const float*)d_in[6];
    const float* beta    = (const float*)d_in[7];
    float*       out     = (float*)d_out;

    k_gemm_hist<<<GEMM_BLOCKS + HIST_BLOCKS, 128>>>(x, W, att_src, att_dst, ei);
    k_offsets<<<(N_NODES + 255) / 256, 256>>>();
    k_fill<<<(NEDGE + 255) / 256, 256>>>(ei);
    k_aggregate<<<(N_NODES + 7) / 8, 256>>>();            // profiled launch (index 3)
    k_final<<<(N_NODES * 32 + 255) / 256, 256>>>(gamma, beta, out);
    k_cleanup<<<(N_NODES + 255) / 256, 256>>>();
}